// round 14
// baseline (speedup 1.0000x reference)
#include <cuda_runtime.h>
#include <cuda_bf16.h>
#include <cstdint>

// Problem constants
#define BB 1024
#define TT 128
#define NN 128
#define MM 256
#define PP 256

// ---------------- scratch (static device globals; no allocation) -------------
__device__ __nv_bfloat16 g_UeT[(size_t)BB * TT * NN];   // [b][s][n]  (bf16 storage)
__device__ float         g_H  [(size_t)BB * TT * MM];   // [b][t][m]  (fp32, for uh_pre)
__device__ __nv_bfloat16 g_Hbf[(size_t)BB * TT * MM];   // bf16 shadow for ctx gather
__device__ __nv_bfloat16 g_UHT[(size_t)BB * MM * TT];   // [b][u][t]  (bf16 storage)
__device__ float g_h[2][BB * MM];               // parity double-buffered
__device__ float g_c[2][BB * MM];
__device__ float g_d[2][BB * PP];
__device__ float g_s[2][BB * PP];
__device__ float g_xt[BB * NN];
__device__ float g_yt[BB];
__device__ float g_wqe_part[4][BB * TT];        // split-K partials (encoder)
__device__ float g_wqd_part[4][BB * MM];        // split-K partials (decoder)

// ---------------- math helpers ----------------------------------------------
__device__ __forceinline__ float ftanh(float x) {
    x = fminf(fmaxf(x, -15.f), 15.f);
    float e = __expf(2.f * x);
    return __fdividef(e - 1.f, e + 1.f);
}
__device__ __forceinline__ float fsig(float x) {
    x = fminf(fmaxf(x, -30.f), 30.f);
    return __fdividef(1.f, 1.f + __expf(-x));
}
__device__ __forceinline__ float ftanh_fast(float x) {
    float y;
    asm("tanh.approx.f32 %0, %1;" : "=f"(y) : "f"(x));
    return y;
}

// 16B-aligned vector read from padded smem tile
#define LDS4(arr, kk, off) (*reinterpret_cast<const float4*>(&arr[kk][off]))

#define MICRO_FMA(acc, a4, b4)                                    \
    do {                                                          \
        float _a[4] = {a4.x, a4.y, a4.z, a4.w};                   \
        float _b[4] = {b4.x, b4.y, b4.z, b4.w};                   \
        _Pragma("unroll")                                         \
        for (int _i = 0; _i < 4; _i++)                            \
            _Pragma("unroll")                                     \
            for (int _j = 0; _j < 4; _j++)                        \
                acc[_i][_j] += _a[_i] * _b[_j];                   \
    } while (0)

// ---------------- precompute UeT[b][s][n] = sum_t Ue[s][t] * enc[b][t][n] ----
__global__ __launch_bounds__(256) void ue_pre_kernel(
    const float* __restrict__ enc_data, const float* __restrict__ Ue)
{
    __shared__ float As[16][68];
    __shared__ float Bs[16][68];
    const int n0 = blockIdx.x * 64;
    const int s0 = blockIdx.y * 64;
    const int b  = blockIdx.z;
    const int tid = threadIdx.x;
    const int tx = tid & 15, ty = tid >> 4;

    if (blockIdx.x == 0 && blockIdx.y == 0) {
        int idx = b * 256 + tid;   // MM == PP == 256
        g_h[0][idx] = 0.f; g_h[1][idx] = 0.f;
        g_c[0][idx] = 0.f; g_c[1][idx] = 0.f;
        g_d[0][idx] = 0.f; g_d[1][idx] = 0.f;
        g_s[0][idx] = 0.f; g_s[1][idx] = 0.f;
    }

    float acc[4][4];
#pragma unroll
    for (int i = 0; i < 4; i++)
#pragma unroll
        for (int j = 0; j < 4; j++) acc[i][j] = 0.f;

    for (int k0 = 0; k0 < TT; k0 += 16) {
#pragma unroll
        for (int i = 0; i < 4; i++) {
            int idx = tid + i * 256;
            int m = idx >> 4, k = idx & 15;
            As[k][m] = Ue[(s0 + m) * TT + (k0 + k)];
        }
#pragma unroll
        for (int i = 0; i < 4; i++) {
            int idx = tid + i * 256;
            int nn2 = idx & 63, k = idx >> 6;
            Bs[k][nn2] = enc_data[((size_t)b * TT + (k0 + k)) * NN + n0 + nn2];
        }
        __syncthreads();
#pragma unroll
        for (int kk = 0; kk < 16; kk++) {
            float4 a4 = LDS4(As, kk, ty * 4);
            float4 b4 = LDS4(Bs, kk, tx * 4);
            MICRO_FMA(acc, a4, b4);
        }
        __syncthreads();
    }
#pragma unroll
    for (int i = 0; i < 4; i++) {
        int s = s0 + ty * 4 + i;
#pragma unroll
        for (int j = 0; j < 4; j++) {
            int n = n0 + tx * 4 + j;
            g_UeT[((size_t)b * TT + s) * NN + n] = __float2bfloat16(acc[i][j]);
        }
    }
}

// ---------------- precompute UHT[b][u][t] = sum_m Ud[u][m] * H[b][t][m] ------
__global__ __launch_bounds__(256) void uh_pre_kernel(const float* __restrict__ Ud)
{
    __shared__ float As[16][68];
    __shared__ float Bs[16][68];
    const int t0 = blockIdx.x * 64;
    const int u0 = blockIdx.y * 64;
    const int b  = blockIdx.z;
    const int tid = threadIdx.x;
    const int tx = tid & 15, ty = tid >> 4;
    float acc[4][4];
#pragma unroll
    for (int i = 0; i < 4; i++)
#pragma unroll
        for (int j = 0; j < 4; j++) acc[i][j] = 0.f;

    for (int k0 = 0; k0 < MM; k0 += 16) {
#pragma unroll
        for (int i = 0; i < 4; i++) {
            int idx = tid + i * 256;
            int m = idx >> 4, k = idx & 15;
            As[k][m] = Ud[(u0 + m) * MM + (k0 + k)];
            Bs[k][m] = g_H[((size_t)b * TT + (t0 + m)) * MM + (k0 + k)];
        }
        __syncthreads();
#pragma unroll
        for (int kk = 0; kk < 16; kk++) {
            float4 a4 = LDS4(As, kk, ty * 4);
            float4 b4 = LDS4(Bs, kk, tx * 4);
            MICRO_FMA(acc, a4, b4);
        }
        __syncthreads();
    }
#pragma unroll
    for (int i = 0; i < 4; i++) {
        int u = u0 + ty * 4 + i;
#pragma unroll
        for (int j = 0; j < 4; j++) {
            int t = t0 + tx * 4 + j;
            g_UHT[((size_t)b * MM + u) * TT + t] = __float2bfloat16(acc[i][j]);
        }
    }
}

// ---------------- encoder wq GEMM (split-K) ----------------------------------
__global__ __launch_bounds__(256) void enc_wq_kernel(const float* __restrict__ We, int p)
{
    __shared__ float As[16][68];
    __shared__ float Bs[16][68];
    const int s0 = blockIdx.x * 64;
    const int b0 = blockIdx.y * 64;
    const int ksl = blockIdx.z;
    const int tid = threadIdx.x;
    const int tx = tid & 15, ty = tid >> 4;
    const int phase = ksl >> 1;
    const int koff = (ksl & 1) * 128;
    const float* q = phase ? g_c[p] : g_h[p];
    float acc[4][4];
#pragma unroll
    for (int i = 0; i < 4; i++)
#pragma unroll
        for (int j = 0; j < 4; j++) acc[i][j] = 0.f;

    for (int k0 = 0; k0 < 128; k0 += 16) {
#pragma unroll
        for (int i = 0; i < 4; i++) {
            int idx = tid + i * 256;
            int m = idx >> 4, k = idx & 15;
            As[k][m] = q[(b0 + m) * MM + koff + k0 + k];
            Bs[k][m] = We[(s0 + m) * (2 * MM) + phase * MM + koff + k0 + k];
        }
        __syncthreads();
#pragma unroll
        for (int kk = 0; kk < 16; kk++) {
            float4 a4 = LDS4(As, kk, ty * 4);
            float4 b4 = LDS4(Bs, kk, tx * 4);
            MICRO_FMA(acc, a4, b4);
        }
        __syncthreads();
    }
#pragma unroll
    for (int i = 0; i < 4; i++) {
        int b = b0 + ty * 4 + i;
#pragma unroll
        for (int j = 0; j < 4; j++) {
            int s = s0 + tx * 4 + j;
            g_wqe_part[ksl][b * TT + s] = acc[i][j];
        }
    }
}

// ---------------- decoder wq GEMM (split-K) ----------------------------------
__global__ __launch_bounds__(256) void dec_wq_kernel(const float* __restrict__ Wd, int p)
{
    __shared__ float As[16][68];
    __shared__ float Bs[16][68];
    const int u0 = blockIdx.x * 64;
    const int b0 = blockIdx.y * 64;
    const int ksl = blockIdx.z;
    const int tid = threadIdx.x;
    const int tx = tid & 15, ty = tid >> 4;
    const int phase = ksl >> 1;
    const int koff = (ksl & 1) * 128;
    const float* q = phase ? g_s[p] : g_d[p];
    float acc[4][4];
#pragma unroll
    for (int i = 0; i < 4; i++)
#pragma unroll
        for (int j = 0; j < 4; j++) acc[i][j] = 0.f;

    for (int k0 = 0; k0 < 128; k0 += 16) {
#pragma unroll
        for (int i = 0; i < 4; i++) {
            int idx = tid + i * 256;
            int m = idx >> 4, k = idx & 15;
            As[k][m] = q[(b0 + m) * PP + koff + k0 + k];
            Bs[k][m] = Wd[(u0 + m) * (2 * PP) + phase * PP + koff + k0 + k];
        }
        __syncthreads();
#pragma unroll
        for (int kk = 0; kk < 16; kk++) {
            float4 a4 = LDS4(As, kk, ty * 4);
            float4 b4 = LDS4(Bs, kk, tx * 4);
            MICRO_FMA(acc, a4, b4);
        }
        __syncthreads();
    }
#pragma unroll
    for (int i = 0; i < 4; i++) {
        int b = b0 + ty * 4 + i;
#pragma unroll
        for (int j = 0; j < 4; j++) {
            int u = u0 + tx * 4 + j;
            g_wqd_part[ksl][b * MM + u] = acc[i][j];
        }
    }
}

// ---------------- encoder attention (one block per batch, 256 threads) -------
__global__ __launch_bounds__(256) void enc_attn_kernel(
    const float* __restrict__ enc_data, const float* __restrict__ ve, int t)
{
    const int b = blockIdx.x;
    const int tid = threadIdx.x;   // 256
    __shared__ float sh_wq[TT], sh_ve[TT];
    __shared__ float sh_px[256], sh_py[256];

    if (tid < TT) {
        int o = b * TT + tid;
        sh_wq[tid] = g_wqe_part[0][o] + g_wqe_part[1][o]
                   + g_wqe_part[2][o] + g_wqe_part[3][o];
        sh_ve[tid] = ve[tid];
    }
    __syncthreads();

    const int npair = tid & 63;        // n = 2*npair, 2*npair+1
    const int sq = tid >> 6;           // s-quarter: 32 s each
    float px = 0.f, py = 0.f;
    {
        const __nv_bfloat162* ue = reinterpret_cast<const __nv_bfloat162*>(
            g_UeT + ((size_t)b * TT + sq * 32) * NN) + npair;
#pragma unroll 8
        for (int s = 0; s < 32; s++) {
            float2 uv = __bfloat1622float2(ue[(size_t)s * (NN / 2)]);
            float w = sh_wq[sq * 32 + s];
            float v = sh_ve[sq * 32 + s];
            px += ftanh_fast(w + uv.x) * v;
            py += ftanh_fast(w + uv.y) * v;
        }
    }
    sh_px[tid] = px;
    sh_py[tid] = py;
    __syncthreads();

    float sc = 0.f;
    if (tid < 128) {
        const float* src = (tid & 1) ? sh_py : sh_px;
        int np = tid >> 1;
        sc = src[np] + src[64 + np] + src[128 + np] + src[192 + np];
    }
    __syncthreads();
    sh_px[tid] = (tid < 128) ? sc : -1e30f;
    __syncthreads();
    for (int off = 128; off > 0; off >>= 1) {
        if (tid < off) sh_px[tid] = fmaxf(sh_px[tid], sh_px[tid + off]);
        __syncthreads();
    }
    float mx = sh_px[0];
    __syncthreads();
    float e = (tid < 128) ? __expf(sc - mx) : 0.f;
    sh_px[tid] = e;
    __syncthreads();
    for (int off = 128; off > 0; off >>= 1) {
        if (tid < off) sh_px[tid] += sh_px[tid + off];
        __syncthreads();
    }
    if (tid < 128) {
        float alpha = __fdividef(e, sh_px[0]);
        g_xt[b * NN + tid] = alpha * enc_data[((size_t)b * TT + t) * NN + tid];
    }
}

// ---------------- encoder LSTM gates GEMM + fused activation -----------------
// Gate-interleaved B layout; 32-row batch tiles (grid 16x32 = 512 blocks) for
// ~2x occupancy vs 64-row tiles. Per-thread microtile acc[2][4].
__global__ __launch_bounds__(256) void enc_gates_act_kernel(
    const float* __restrict__ Wih, const float* __restrict__ Whh,
    const float* __restrict__ bih, const float* __restrict__ bhh,
    int t, int p)
{
    __shared__ float As[2][16][36];   // 32 batch rows (+pad)
    __shared__ float Bs[2][16][68];   // 64 gate-interleaved cols (+pad)
    const int j0 = blockIdx.x * 16;
    const int b0 = blockIdx.y * 32;
    const int tid = threadIdx.x;
    const int tx = tid & 15, ty = tid >> 4;
    float acc[2][4];
#pragma unroll
    for (int i = 0; i < 2; i++)
#pragma unroll
        for (int j = 0; j < 4; j++) acc[i][j] = 0.f;

    const float* h_in = g_h[p];
    const float* c_in = g_c[p];
    float* h_out = g_h[p ^ 1];
    float* c_out = g_c[p ^ 1];

    // 24 k-chunks: 0..7 -> x @ Wih (K=128), 8..23 -> h @ Whh (K=256)
#define ENC_LOAD_CHUNK(buf, cidx)                                              \
    do {                                                                       \
        int _k0 = (cidx) * 16;                                                 \
        _Pragma("unroll")                                                      \
        for (int _i = 0; _i < 2; _i++) {                                       \
            int _idx = tid + _i * 256;                                         \
            int _r = _idx >> 4, _k = _idx & 15;                                \
            As[buf][_k][_r] = ((cidx) < 8)                                     \
                ? g_xt[(b0 + _r) * NN + _k0 + _k]                              \
                : h_in[(b0 + _r) * MM + (_k0 - 128) + _k];                     \
        }                                                                      \
        _Pragma("unroll")                                                      \
        for (int _i = 0; _i < 4; _i++) {                                       \
            int _idx = tid + _i * 256;                                         \
            int _cc = _idx >> 4, _k = _idx & 15;                               \
            int _jj = _cc >> 2, _gate = _cc & 3;                               \
            Bs[buf][_k][_cc] = ((cidx) < 8)                                    \
                ? Wih[(_gate * 256 + j0 + _jj) * NN + _k0 + _k]                \
                : Whh[(_gate * 256 + j0 + _jj) * MM + (_k0 - 128) + _k];       \
        }                                                                      \
    } while (0)

    ENC_LOAD_CHUNK(0, 0);
    __syncthreads();
    for (int c = 0; c < 24; c++) {
        int cur = c & 1;
        if (c < 23) ENC_LOAD_CHUNK(cur ^ 1, c + 1);
#pragma unroll
        for (int kk = 0; kk < 16; kk++) {
            float2 a2 = *reinterpret_cast<const float2*>(&As[cur][kk][ty * 2]);
            float4 b4 = LDS4(Bs[cur], kk, tx * 4);
            float bb[4] = {b4.x, b4.y, b4.z, b4.w};
#pragma unroll
            for (int j = 0; j < 4; j++) {
                acc[0][j] += a2.x * bb[j];
                acc[1][j] += a2.y * bb[j];
            }
        }
        __syncthreads();
    }
#undef ENC_LOAD_CHUNK

    const int col0 = j0 + tx;
    const float bi0 = bih[col0]       + bhh[col0];
    const float bf0 = bih[256 + col0] + bhh[256 + col0];
    const float bg0 = bih[512 + col0] + bhh[512 + col0];
    const float bo0 = bih[768 + col0] + bhh[768 + col0];
#pragma unroll
    for (int i = 0; i < 2; i++) {
        int b = b0 + ty * 2 + i;
        int sidx = b * MM + col0;
        float gi = acc[i][0] + bi0;
        float gf = acc[i][1] + bf0;
        float gg = acc[i][2] + bg0;
        float go = acc[i][3] + bo0;
        float c_old = c_in[sidx];
        float cn = fsig(gf) * c_old + fsig(gi) * ftanh(gg);
        float hn = fsig(go) * ftanh(cn);
        c_out[sidx] = cn;
        h_out[sidx] = hn;
        size_t hidx = ((size_t)b * TT + t) * MM + col0;
        g_H[hidx] = hn;
        g_Hbf[hidx] = __float2bfloat16(hn);
    }
}

// ---------------- decoder attention (one block per batch, 256 threads) -------
__global__ __launch_bounds__(256) void dec_attn_kernel(
    const float* __restrict__ dec_data, const float* __restrict__ vd,
    const float* __restrict__ wt_w, const float* __restrict__ wt_b,
    int step, int final_mode, int p,
    const float* __restrict__ l1_w, const float* __restrict__ l1_b,
    const float* __restrict__ l2_w, const float* __restrict__ l2_b,
    float* __restrict__ out)
{
    const int b = blockIdx.x;
    const int tid = threadIdx.x;  // 256
    __shared__ float sh_wq[MM], sh_vd[MM];
    __shared__ float sh_beta[TT];
    __shared__ float sh_px[256], sh_py[256];
    __shared__ float sh_v[512];

    {
        int o = b * MM + tid;
        sh_wq[tid] = g_wqd_part[0][o] + g_wqd_part[1][o]
                   + g_wqd_part[2][o] + g_wqd_part[3][o];
    }
    sh_vd[tid] = vd[tid];
    __syncthreads();

    // score: thread owns t-pair (2*tpair, 2*tpair+1) for one u-quarter (64 u)
    const int tpair = tid & 63;
    const int uq = tid >> 6;
    float px = 0.f, py = 0.f;
    {
        const __nv_bfloat162* uh = reinterpret_cast<const __nv_bfloat162*>(
            g_UHT + ((size_t)b * MM + uq * 64) * TT) + tpair;
#pragma unroll 8
        for (int u = 0; u < 64; u++) {
            float2 uv = __bfloat1622float2(uh[(size_t)u * (TT / 2)]);
            float w = sh_wq[uq * 64 + u];
            float v = sh_vd[uq * 64 + u];
            px += ftanh_fast(w + uv.x) * v;
            py += ftanh_fast(w + uv.y) * v;
        }
    }
    sh_px[tid] = px;
    sh_py[tid] = py;
    __syncthreads();

    float sc = 0.f;
    if (tid < 128) {
        const float* src = (tid & 1) ? sh_py : sh_px;
        int tp = tid >> 1;
        sc = src[tp] + src[64 + tp] + src[128 + tp] + src[192 + tp];
    }
    __syncthreads();
    sh_px[tid] = (tid < 128) ? sc : -1e30f;
    __syncthreads();
    for (int off = 128; off > 0; off >>= 1) {
        if (tid < off) sh_px[tid] = fmaxf(sh_px[tid], sh_px[tid + off]);
        __syncthreads();
    }
    float mx = sh_px[0];
    __syncthreads();
    float e = (tid < 128) ? __expf(sc - mx) : 0.f;
    sh_px[tid] = e;
    __syncthreads();
    for (int off = 128; off > 0; off >>= 1) {
        if (tid < off) sh_px[tid] += sh_px[tid + off];
        __syncthreads();
    }
    float ssum = sh_px[0];
    __syncthreads();
    if (tid < 128) sh_beta[tid] = __fdividef(e, ssum);
    __syncthreads();

    // ctx: thread owns m-pair (2*mpair, 2*mpair+1) for one t-half (64 t)
    const int mpair = tid & 127;
    const int th = tid >> 7;
    float cx = 0.f, cy = 0.f;
    {
        const __nv_bfloat162* hrow = reinterpret_cast<const __nv_bfloat162*>(
            g_Hbf + ((size_t)b * TT + th * 64) * MM) + mpair;
#pragma unroll 8
        for (int t2 = 0; t2 < 64; t2++) {
            float2 hv = __bfloat1622float2(hrow[(size_t)t2 * (MM / 2)]);
            float beta = sh_beta[th * 64 + t2];
            cx += beta * hv.x;
            cy += beta * hv.y;
        }
    }
    sh_px[tid] = cx;
    sh_py[tid] = cy;
    __syncthreads();
    float ctx;
    {
        const float* src = (tid & 1) ? sh_py : sh_px;
        int mp = tid >> 1;
        ctx = src[mp] + src[128 + mp];
    }
    __syncthreads();

    if (!final_mode) {
        sh_px[tid] = ctx * wt_w[1 + tid];
        __syncthreads();
        for (int off = 128; off > 0; off >>= 1) {
            if (tid < off) sh_px[tid] += sh_px[tid + off];
            __syncthreads();
        }
        if (tid == 0) {
            float y = dec_data[(size_t)b * TT + step];
            g_yt[b] = sh_px[0] + y * wt_w[0] + wt_b[0];
        }
        return;
    }

    // final head: v = [d | ctx];  out[b] = relu(v @ l1^T + b1) @ l2^T + b2
    sh_v[tid] = g_d[p][b * PP + tid];
    sh_v[256 + tid] = ctx;
    __syncthreads();
    float a = l1_b[tid];
    const float* w = l1_w + tid * 512;
#pragma unroll 8
    for (int k = 0; k < 512; k++) a += sh_v[k] * w[k];
    a = fmaxf(a, 0.f);
    sh_px[tid] = a * l2_w[tid];
    __syncthreads();
    for (int off = 128; off > 0; off >>= 1) {
        if (tid < off) sh_px[tid] += sh_px[tid + off];
        __syncthreads();
    }
    if (tid == 0) out[b] = sh_px[0] + l2_b[0];
}

// ---------------- decoder LSTM gates GEMM + fused activation -----------------
// 32-row batch tiles (grid 16x32 = 512 blocks), acc[2][4] microtile.
__global__ __launch_bounds__(256) void dec_gates_act_kernel(
    const float* __restrict__ Wih, const float* __restrict__ Whh,
    const float* __restrict__ bih, const float* __restrict__ bhh, int p)
{
    __shared__ float As[2][16][36];
    __shared__ float Bs[2][16][68];
    const int j0 = blockIdx.x * 16;
    const int b0 = blockIdx.y * 32;
    const int tid = threadIdx.x;
    const int tx = tid & 15, ty = tid >> 4;
    float acc[2][4];
#pragma unroll
    for (int i = 0; i < 2; i++)
#pragma unroll
        for (int j = 0; j < 4; j++) acc[i][j] = 0.f;

    const float* d_in = g_d[p];
    const float* s_in = g_s[p];
    float* d_out = g_d[p ^ 1];
    float* s_out = g_s[p ^ 1];

#define DEC_LOAD_CHUNK(buf, cidx)                                              \
    do {                                                                       \
        int _k0 = (cidx) * 16;                                                 \
        _Pragma("unroll")                                                      \
        for (int _i = 0; _i < 2; _i++) {                                       \
            int _idx = tid + _i * 256;                                         \
            int _r = _idx >> 4, _k = _idx & 15;                                \
            As[buf][_k][_r] = d_in[(b0 + _r) * PP + _k0 + _k];                 \
        }                                                                      \
        _Pragma("unroll")                                                      \
        for (int _i = 0; _i < 4; _i++) {                                       \
            int _idx = tid + _i * 256;                                         \
            int _cc = _idx >> 4, _k = _idx & 15;                               \
            int _jj = _cc >> 2, _gate = _cc & 3;                               \
            Bs[buf][_k][_cc] = Whh[(_gate * 256 + j0 + _jj) * PP + _k0 + _k];  \
        }                                                                      \
    } while (0)

    DEC_LOAD_CHUNK(0, 0);
    __syncthreads();
    for (int c = 0; c < 16; c++) {
        int cur = c & 1;
        if (c < 15) DEC_LOAD_CHUNK(cur ^ 1, c + 1);
#pragma unroll
        for (int kk = 0; kk < 16; kk++) {
            float2 a2 = *reinterpret_cast<const float2*>(&As[cur][kk][ty * 2]);
            float4 b4 = LDS4(Bs[cur], kk, tx * 4);
            float bb[4] = {b4.x, b4.y, b4.z, b4.w};
#pragma unroll
            for (int j = 0; j < 4; j++) {
                acc[0][j] += a2.x * bb[j];
                acc[1][j] += a2.y * bb[j];
            }
        }
        __syncthreads();
    }
#undef DEC_LOAD_CHUNK

    const int col0 = j0 + tx;
    const float wi0 = Wih[col0];
    const float wf0 = Wih[256 + col0];
    const float wg0 = Wih[512 + col0];
    const float wo0 = Wih[768 + col0];
    const float bi0 = bih[col0]       + bhh[col0];
    const float bf0 = bih[256 + col0] + bhh[256 + col0];
    const float bg0 = bih[512 + col0] + bhh[512 + col0];
    const float bo0 = bih[768 + col0] + bhh[768 + col0];
#pragma unroll
    for (int i = 0; i < 2; i++) {
        int b = b0 + ty * 2 + i;
        float yt = g_yt[b];
        int sidx = b * PP + col0;
        float gi = acc[i][0] + yt * wi0 + bi0;
        float gf = acc[i][1] + yt * wf0 + bf0;
        float gg = acc[i][2] + yt * wg0 + bg0;
        float go = acc[i][3] + yt * wo0 + bo0;
        float s_old = s_in[sidx];
        float sn = fsig(gf) * s_old + fsig(gi) * ftanh(gg);
        float dn = fsig(go) * ftanh(sn);
        s_out[sidx] = sn;
        d_out[sidx] = dn;
    }
}

// ---------------- launch -----------------------------------------------------
extern "C" void kernel_launch(void* const* d_in, const int* in_sizes, int n_in,
                              void* d_out, int out_size)
{
    const float* enc_data = (const float*)d_in[0];
    const float* dec_data = (const float*)d_in[1];
    const float* enc_Wih  = (const float*)d_in[2];
    const float* enc_Whh  = (const float*)d_in[3];
    const float* enc_bih  = (const float*)d_in[4];
    const float* enc_bhh  = (const float*)d_in[5];
    const float* We       = (const float*)d_in[6];
    const float* Ue       = (const float*)d_in[7];
    const float* ve       = (const float*)d_in[8];
    const float* Wd       = (const float*)d_in[9];
    const float* Ud       = (const float*)d_in[10];
    const float* vd       = (const float*)d_in[11];
    const float* wt_w     = (const float*)d_in[12];
    const float* wt_b     = (const float*)d_in[13];
    const float* dec_Wih  = (const float*)d_in[14];
    const float* dec_Whh  = (const float*)d_in[15];
    const float* dec_bih  = (const float*)d_in[16];
    const float* dec_bhh  = (const float*)d_in[17];
    const float* l1_w     = (const float*)d_in[18];
    const float* l1_b     = (const float*)d_in[19];
    const float* l2_w     = (const float*)d_in[20];
    const float* l2_b     = (const float*)d_in[21];
    float* out = (float*)d_out;

    ue_pre_kernel<<<dim3(NN / 64, TT / 64, BB), 256>>>(enc_data, Ue);

    for (int t = 0; t < TT; t++) {
        int p = t & 1;
        enc_wq_kernel<<<dim3(TT / 64, BB / 64, 4), 256>>>(We, p);
        enc_attn_kernel<<<BB, 256>>>(enc_data, ve, t);
        enc_gates_act_kernel<<<dim3(16, 32), 256>>>(enc_Wih, enc_Whh, enc_bih, enc_bhh, t, p);
    }

    uh_pre_kernel<<<dim3(TT / 64, MM / 64, BB), 256>>>(Ud);

    for (int step = 0; step < TT - 1; step++) {
        int p = step & 1;
        dec_wq_kernel<<<dim3(MM / 64, BB / 64, 4), 256>>>(Wd, p);
        dec_attn_kernel<<<BB, 256>>>(dec_data, vd, wt_w, wt_b, step, 0, p,
                                     l1_w, l1_b, l2_w, l2_b, out);
        dec_gates_act_kernel<<<dim3(16, 32), 256>>>(dec_Wih, dec_Whh, dec_bih, dec_bhh, p);
    }

    // final attention + head with last decoder state (parity 127&1 = 1)
    dec_wq_kernel<<<dim3(MM / 64, BB / 64, 4), 256>>>(Wd, 1);
    dec_attn_kernel<<<BB, 256>>>(dec_data, vd, wt_w, wt_b, 0, 1, 1,
                                 l1_w, l1_b, l2_w, l2_b, out);
}

// round 16
// speedup vs baseline: 1.2154x; 1.2154x over previous
#include <cuda_runtime.h>
#include <cuda_bf16.h>
#include <cstdint>

// Problem constants
#define BB 1024
#define TT 128
#define NN 128
#define MM 256
#define PP 256

// ---------------- scratch (static device globals; no allocation) -------------
__device__ __nv_bfloat16 g_UeT[(size_t)BB * TT * NN];   // [b][s][n]  (bf16 storage)
__device__ float         g_H  [(size_t)BB * TT * MM];   // [b][t][m]  (fp32, for uh_pre)
__device__ __nv_bfloat16 g_Hbf[(size_t)BB * TT * MM];   // bf16 shadow for ctx gather
__device__ __nv_bfloat16 g_UHT[(size_t)BB * MM * TT];   // [b][u][t]  (bf16 storage)
__device__ float g_h[2][BB * MM];               // parity double-buffered
__device__ float g_c[2][BB * MM];
__device__ float g_d[2][BB * PP];
__device__ float g_s[2][BB * PP];
__device__ float g_xt[BB * NN];
__device__ float g_yt[BB];
__device__ float g_wqe_part[4][BB * TT];        // split-K partials (encoder)
__device__ float g_wqd_part[4][BB * MM];        // split-K partials (decoder)

// ---------------- math helpers ----------------------------------------------
__device__ __forceinline__ float ftanh(float x) {
    x = fminf(fmaxf(x, -15.f), 15.f);
    float e = __expf(2.f * x);
    return __fdividef(e - 1.f, e + 1.f);
}
__device__ __forceinline__ float fsig(float x) {
    x = fminf(fmaxf(x, -30.f), 30.f);
    return __fdividef(1.f, 1.f + __expf(-x));
}
__device__ __forceinline__ float ftanh_fast(float x) {
    float y;
    asm("tanh.approx.f32 %0, %1;" : "=f"(y) : "f"(x));
    return y;
}
__device__ __forceinline__ uint32_t f2tf32(float v) {
    uint32_t u;
    asm("cvt.rna.tf32.f32 %0, %1;" : "=r"(u) : "f"(v));
    return u;
}
__device__ __forceinline__ void mma_tf32(float* d,
    uint32_t a0, uint32_t a1, uint32_t a2, uint32_t a3,
    uint32_t b0, uint32_t b1)
{
    asm volatile(
        "mma.sync.aligned.m16n8k8.row.col.f32.tf32.tf32.f32 "
        "{%0,%1,%2,%3}, {%4,%5,%6,%7}, {%8,%9}, {%0,%1,%2,%3};\n"
        : "+f"(d[0]), "+f"(d[1]), "+f"(d[2]), "+f"(d[3])
        : "r"(a0), "r"(a1), "r"(a2), "r"(a3), "r"(b0), "r"(b1));
}

// 16B-aligned vector read from padded smem tile
#define LDS4(arr, kk, off) (*reinterpret_cast<const float4*>(&arr[kk][off]))

#define MICRO_FMA(acc, a4, b4)                                    \
    do {                                                          \
        float _a[4] = {a4.x, a4.y, a4.z, a4.w};                   \
        float _b[4] = {b4.x, b4.y, b4.z, b4.w};                   \
        _Pragma("unroll")                                         \
        for (int _i = 0; _i < 4; _i++)                            \
            _Pragma("unroll")                                     \
            for (int _j = 0; _j < 4; _j++)                        \
                acc[_i][_j] += _a[_i] * _b[_j];                   \
    } while (0)

// ---------------- precompute UeT[b][s][n] = sum_t Ue[s][t] * enc[b][t][n] ----
__global__ __launch_bounds__(256) void ue_pre_kernel(
    const float* __restrict__ enc_data, const float* __restrict__ Ue)
{
    __shared__ float As[16][68];
    __shared__ float Bs[16][68];
    const int n0 = blockIdx.x * 64;
    const int s0 = blockIdx.y * 64;
    const int b  = blockIdx.z;
    const int tid = threadIdx.x;
    const int tx = tid & 15, ty = tid >> 4;

    if (blockIdx.x == 0 && blockIdx.y == 0) {
        int idx = b * 256 + tid;   // MM == PP == 256
        g_h[0][idx] = 0.f; g_h[1][idx] = 0.f;
        g_c[0][idx] = 0.f; g_c[1][idx] = 0.f;
        g_d[0][idx] = 0.f; g_d[1][idx] = 0.f;
        g_s[0][idx] = 0.f; g_s[1][idx] = 0.f;
    }

    float acc[4][4];
#pragma unroll
    for (int i = 0; i < 4; i++)
#pragma unroll
        for (int j = 0; j < 4; j++) acc[i][j] = 0.f;

    for (int k0 = 0; k0 < TT; k0 += 16) {
#pragma unroll
        for (int i = 0; i < 4; i++) {
            int idx = tid + i * 256;
            int m = idx >> 4, k = idx & 15;
            As[k][m] = Ue[(s0 + m) * TT + (k0 + k)];
        }
#pragma unroll
        for (int i = 0; i < 4; i++) {
            int idx = tid + i * 256;
            int nn2 = idx & 63, k = idx >> 6;
            Bs[k][nn2] = enc_data[((size_t)b * TT + (k0 + k)) * NN + n0 + nn2];
        }
        __syncthreads();
#pragma unroll
        for (int kk = 0; kk < 16; kk++) {
            float4 a4 = LDS4(As, kk, ty * 4);
            float4 b4 = LDS4(Bs, kk, tx * 4);
            MICRO_FMA(acc, a4, b4);
        }
        __syncthreads();
    }
#pragma unroll
    for (int i = 0; i < 4; i++) {
        int s = s0 + ty * 4 + i;
#pragma unroll
        for (int j = 0; j < 4; j++) {
            int n = n0 + tx * 4 + j;
            g_UeT[((size_t)b * TT + s) * NN + n] = __float2bfloat16(acc[i][j]);
        }
    }
}

// ---------------- precompute UHT[b][u][t] = sum_m Ud[u][m] * H[b][t][m] ------
__global__ __launch_bounds__(256) void uh_pre_kernel(const float* __restrict__ Ud)
{
    __shared__ float As[16][68];
    __shared__ float Bs[16][68];
    const int t0 = blockIdx.x * 64;
    const int u0 = blockIdx.y * 64;
    const int b  = blockIdx.z;
    const int tid = threadIdx.x;
    const int tx = tid & 15, ty = tid >> 4;
    float acc[4][4];
#pragma unroll
    for (int i = 0; i < 4; i++)
#pragma unroll
        for (int j = 0; j < 4; j++) acc[i][j] = 0.f;

    for (int k0 = 0; k0 < MM; k0 += 16) {
#pragma unroll
        for (int i = 0; i < 4; i++) {
            int idx = tid + i * 256;
            int m = idx >> 4, k = idx & 15;
            As[k][m] = Ud[(u0 + m) * MM + (k0 + k)];
            Bs[k][m] = g_H[((size_t)b * TT + (t0 + m)) * MM + (k0 + k)];
        }
        __syncthreads();
#pragma unroll
        for (int kk = 0; kk < 16; kk++) {
            float4 a4 = LDS4(As, kk, ty * 4);
            float4 b4 = LDS4(Bs, kk, tx * 4);
            MICRO_FMA(acc, a4, b4);
        }
        __syncthreads();
    }
#pragma unroll
    for (int i = 0; i < 4; i++) {
        int u = u0 + ty * 4 + i;
#pragma unroll
        for (int j = 0; j < 4; j++) {
            int t = t0 + tx * 4 + j;
            g_UHT[((size_t)b * MM + u) * TT + t] = __float2bfloat16(acc[i][j]);
        }
    }
}

// ---------------- encoder wq GEMM (split-K) ----------------------------------
__global__ __launch_bounds__(256) void enc_wq_kernel(const float* __restrict__ We, int p)
{
    __shared__ float As[16][68];
    __shared__ float Bs[16][68];
    const int s0 = blockIdx.x * 64;
    const int b0 = blockIdx.y * 64;
    const int ksl = blockIdx.z;
    const int tid = threadIdx.x;
    const int tx = tid & 15, ty = tid >> 4;
    const int phase = ksl >> 1;
    const int koff = (ksl & 1) * 128;
    const float* q = phase ? g_c[p] : g_h[p];
    float acc[4][4];
#pragma unroll
    for (int i = 0; i < 4; i++)
#pragma unroll
        for (int j = 0; j < 4; j++) acc[i][j] = 0.f;

    for (int k0 = 0; k0 < 128; k0 += 16) {
#pragma unroll
        for (int i = 0; i < 4; i++) {
            int idx = tid + i * 256;
            int m = idx >> 4, k = idx & 15;
            As[k][m] = q[(b0 + m) * MM + koff + k0 + k];
            Bs[k][m] = We[(s0 + m) * (2 * MM) + phase * MM + koff + k0 + k];
        }
        __syncthreads();
#pragma unroll
        for (int kk = 0; kk < 16; kk++) {
            float4 a4 = LDS4(As, kk, ty * 4);
            float4 b4 = LDS4(Bs, kk, tx * 4);
            MICRO_FMA(acc, a4, b4);
        }
        __syncthreads();
    }
#pragma unroll
    for (int i = 0; i < 4; i++) {
        int b = b0 + ty * 4 + i;
#pragma unroll
        for (int j = 0; j < 4; j++) {
            int s = s0 + tx * 4 + j;
            g_wqe_part[ksl][b * TT + s] = acc[i][j];
        }
    }
}

// ---------------- decoder wq GEMM (split-K) ----------------------------------
__global__ __launch_bounds__(256) void dec_wq_kernel(const float* __restrict__ Wd, int p)
{
    __shared__ float As[16][68];
    __shared__ float Bs[16][68];
    const int u0 = blockIdx.x * 64;
    const int b0 = blockIdx.y * 64;
    const int ksl = blockIdx.z;
    const int tid = threadIdx.x;
    const int tx = tid & 15, ty = tid >> 4;
    const int phase = ksl >> 1;
    const int koff = (ksl & 1) * 128;
    const float* q = phase ? g_s[p] : g_d[p];
    float acc[4][4];
#pragma unroll
    for (int i = 0; i < 4; i++)
#pragma unroll
        for (int j = 0; j < 4; j++) acc[i][j] = 0.f;

    for (int k0 = 0; k0 < 128; k0 += 16) {
#pragma unroll
        for (int i = 0; i < 4; i++) {
            int idx = tid + i * 256;
            int m = idx >> 4, k = idx & 15;
            As[k][m] = q[(b0 + m) * PP + koff + k0 + k];
            Bs[k][m] = Wd[(u0 + m) * (2 * PP) + phase * PP + koff + k0 + k];
        }
        __syncthreads();
#pragma unroll
        for (int kk = 0; kk < 16; kk++) {
            float4 a4 = LDS4(As, kk, ty * 4);
            float4 b4 = LDS4(Bs, kk, tx * 4);
            MICRO_FMA(acc, a4, b4);
        }
        __syncthreads();
    }
#pragma unroll
    for (int i = 0; i < 4; i++) {
        int b = b0 + ty * 4 + i;
#pragma unroll
        for (int j = 0; j < 4; j++) {
            int u = u0 + tx * 4 + j;
            g_wqd_part[ksl][b * MM + u] = acc[i][j];
        }
    }
}

// ---------------- encoder attention (one block per batch, 256 threads) -------
__global__ __launch_bounds__(256) void enc_attn_kernel(
    const float* __restrict__ enc_data, const float* __restrict__ ve, int t)
{
    const int b = blockIdx.x;
    const int tid = threadIdx.x;   // 256
    __shared__ float sh_wq[TT], sh_ve[TT];
    __shared__ float sh_px[256], sh_py[256];

    if (tid < TT) {
        int o = b * TT + tid;
        sh_wq[tid] = g_wqe_part[0][o] + g_wqe_part[1][o]
                   + g_wqe_part[2][o] + g_wqe_part[3][o];
        sh_ve[tid] = ve[tid];
    }
    __syncthreads();

    const int npair = tid & 63;        // n = 2*npair, 2*npair+1
    const int sq = tid >> 6;           // s-quarter: 32 s each
    float px = 0.f, py = 0.f;
    {
        const __nv_bfloat162* ue = reinterpret_cast<const __nv_bfloat162*>(
            g_UeT + ((size_t)b * TT + sq * 32) * NN) + npair;
#pragma unroll 8
        for (int s = 0; s < 32; s++) {
            float2 uv = __bfloat1622float2(ue[(size_t)s * (NN / 2)]);
            float w = sh_wq[sq * 32 + s];
            float v = sh_ve[sq * 32 + s];
            px += ftanh_fast(w + uv.x) * v;
            py += ftanh_fast(w + uv.y) * v;
        }
    }
    sh_px[tid] = px;
    sh_py[tid] = py;
    __syncthreads();

    float sc = 0.f;
    if (tid < 128) {
        const float* src = (tid & 1) ? sh_py : sh_px;
        int np = tid >> 1;
        sc = src[np] + src[64 + np] + src[128 + np] + src[192 + np];
    }
    __syncthreads();
    sh_px[tid] = (tid < 128) ? sc : -1e30f;
    __syncthreads();
    for (int off = 128; off > 0; off >>= 1) {
        if (tid < off) sh_px[tid] = fmaxf(sh_px[tid], sh_px[tid + off]);
        __syncthreads();
    }
    float mx = sh_px[0];
    __syncthreads();
    float e = (tid < 128) ? __expf(sc - mx) : 0.f;
    sh_px[tid] = e;
    __syncthreads();
    for (int off = 128; off > 0; off >>= 1) {
        if (tid < off) sh_px[tid] += sh_px[tid + off];
        __syncthreads();
    }
    if (tid < 128) {
        float alpha = __fdividef(e, sh_px[0]);
        g_xt[b * NN + tid] = alpha * enc_data[((size_t)b * TT + t) * NN + tid];
    }
}

// ---------------- encoder LSTM gates: tf32 tensor-core MMA + fused act -------
// Block tile 64 batches x 64 gate-interleaved cols; 8 warps as 4(m) x 2(n);
// mma.sync.m16n8k8 tf32 with fp32 accumulate; C staged via Sg for activation.
__global__ __launch_bounds__(256) void enc_gates_act_kernel(
    const float* __restrict__ Wih, const float* __restrict__ Whh,
    const float* __restrict__ bih, const float* __restrict__ bhh,
    int t, int p)
{
    __shared__ uint32_t As[64][20];   // [m][k]  tf32 bits, conflict-free pad
    __shared__ uint32_t Bs[16][72];   // [k][cc] tf32 bits
    __shared__ float Sg[64][68];
    const int j0 = blockIdx.x * 16;
    const int b0 = blockIdx.y * 64;
    const int tid = threadIdx.x;
    const int lane = tid & 31;
    const int warp = tid >> 5;
    const int mw = (warp & 3) * 16;
    const int nw = (warp >> 2) * 32;
    const int gid = lane >> 2;
    const int tig = lane & 3;

    const float* h_in = g_h[p];
    const float* c_in = g_c[p];
    float* h_out = g_h[p ^ 1];
    float* c_out = g_c[p ^ 1];

    float acc[4][4];
#pragma unroll
    for (int i = 0; i < 4; i++)
#pragma unroll
        for (int j = 0; j < 4; j++) acc[i][j] = 0.f;

    // 24 k-chunks of 16: 0..7 -> xt @ Wih (K=128), 8..23 -> h @ Whh (K=256)
    for (int c = 0; c < 24; c++) {
        int k0 = c * 16;
#pragma unroll
        for (int i = 0; i < 4; i++) {
            int idx = tid + i * 256;
            int m = idx >> 4, k = idx & 15;
            float v = (c < 8) ? g_xt[(b0 + m) * NN + k0 + k]
                              : h_in[(b0 + m) * MM + (k0 - 128) + k];
            As[m][k] = f2tf32(v);
        }
#pragma unroll
        for (int i = 0; i < 4; i++) {
            int idx = tid + i * 256;
            int cc = idx >> 4, k = idx & 15;
            int jj = cc >> 2, gate = cc & 3;
            float wv = (c < 8) ? Wih[(gate * 256 + j0 + jj) * NN + k0 + k]
                               : Whh[(gate * 256 + j0 + jj) * MM + (k0 - 128) + k];
            Bs[k][cc] = f2tf32(wv);
        }
        __syncthreads();
#pragma unroll
        for (int ks = 0; ks < 16; ks += 8) {
            uint32_t a0 = As[mw + gid][ks + tig];
            uint32_t a1 = As[mw + 8 + gid][ks + tig];
            uint32_t a2 = As[mw + gid][ks + 4 + tig];
            uint32_t a3 = As[mw + 8 + gid][ks + 4 + tig];
#pragma unroll
            for (int nt = 0; nt < 4; nt++) {
                uint32_t b0r = Bs[ks + tig][nw + nt * 8 + gid];
                uint32_t b1r = Bs[ks + 4 + tig][nw + nt * 8 + gid];
                mma_tf32(acc[nt], a0, a1, a2, a3, b0r, b1r);
            }
        }
        __syncthreads();
    }

    // stage C fragments
#pragma unroll
    for (int nt = 0; nt < 4; nt++) {
        int col = nw + nt * 8 + tig * 2;
        int row = mw + gid;
        Sg[row][col]     = acc[nt][0];
        Sg[row][col + 1] = acc[nt][1];
        Sg[row + 8][col]     = acc[nt][2];
        Sg[row + 8][col + 1] = acc[nt][3];
    }
    __syncthreads();

    // activation: thread handles row r for 4 jj values
    {
        int r = tid & 63;
        int b = b0 + r;
#pragma unroll
        for (int jj = tid >> 6; jj < 16; jj += 4) {
            float4 g4 = *reinterpret_cast<const float4*>(&Sg[r][jj * 4]);
            int col0 = j0 + jj;
            float gi = g4.x + bih[col0]       + bhh[col0];
            float gf = g4.y + bih[256 + col0] + bhh[256 + col0];
            float gg = g4.z + bih[512 + col0] + bhh[512 + col0];
            float go = g4.w + bih[768 + col0] + bhh[768 + col0];
            int sidx = b * MM + col0;
            float c_old = c_in[sidx];
            float cn = fsig(gf) * c_old + fsig(gi) * ftanh(gg);
            float hn = fsig(go) * ftanh(cn);
            c_out[sidx] = cn;
            h_out[sidx] = hn;
            size_t hidx = ((size_t)b * TT + t) * MM + col0;
            g_H[hidx] = hn;
            g_Hbf[hidx] = __float2bfloat16(hn);
        }
    }
}

// ---------------- decoder attention (one block per batch, 256 threads) -------
__global__ __launch_bounds__(256) void dec_attn_kernel(
    const float* __restrict__ dec_data, const float* __restrict__ vd,
    const float* __restrict__ wt_w, const float* __restrict__ wt_b,
    int step, int final_mode, int p,
    const float* __restrict__ l1_w, const float* __restrict__ l1_b,
    const float* __restrict__ l2_w, const float* __restrict__ l2_b,
    float* __restrict__ out)
{
    const int b = blockIdx.x;
    const int tid = threadIdx.x;  // 256
    __shared__ float sh_wq[MM], sh_vd[MM];
    __shared__ float sh_beta[TT];
    __shared__ float sh_px[256], sh_py[256];
    __shared__ float sh_v[512];

    {
        int o = b * MM + tid;
        sh_wq[tid] = g_wqd_part[0][o] + g_wqd_part[1][o]
                   + g_wqd_part[2][o] + g_wqd_part[3][o];
    }
    sh_vd[tid] = vd[tid];
    __syncthreads();

    const int tpair = tid & 63;
    const int uq = tid >> 6;
    float px = 0.f, py = 0.f;
    {
        const __nv_bfloat162* uh = reinterpret_cast<const __nv_bfloat162*>(
            g_UHT + ((size_t)b * MM + uq * 64) * TT) + tpair;
#pragma unroll 8
        for (int u = 0; u < 64; u++) {
            float2 uv = __bfloat1622float2(uh[(size_t)u * (TT / 2)]);
            float w = sh_wq[uq * 64 + u];
            float v = sh_vd[uq * 64 + u];
            px += ftanh_fast(w + uv.x) * v;
            py += ftanh_fast(w + uv.y) * v;
        }
    }
    sh_px[tid] = px;
    sh_py[tid] = py;
    __syncthreads();

    float sc = 0.f;
    if (tid < 128) {
        const float* src = (tid & 1) ? sh_py : sh_px;
        int tp = tid >> 1;
        sc = src[tp] + src[64 + tp] + src[128 + tp] + src[192 + tp];
    }
    __syncthreads();
    sh_px[tid] = (tid < 128) ? sc : -1e30f;
    __syncthreads();
    for (int off = 128; off > 0; off >>= 1) {
        if (tid < off) sh_px[tid] = fmaxf(sh_px[tid], sh_px[tid + off]);
        __syncthreads();
    }
    float mx = sh_px[0];
    __syncthreads();
    float e = (tid < 128) ? __expf(sc - mx) : 0.f;
    sh_px[tid] = e;
    __syncthreads();
    for (int off = 128; off > 0; off >>= 1) {
        if (tid < off) sh_px[tid] += sh_px[tid + off];
        __syncthreads();
    }
    float ssum = sh_px[0];
    __syncthreads();
    if (tid < 128) sh_beta[tid] = __fdividef(e, ssum);
    __syncthreads();

    const int mpair = tid & 127;
    const int th = tid >> 7;
    float cx = 0.f, cy = 0.f;
    {
        const __nv_bfloat162* hrow = reinterpret_cast<const __nv_bfloat162*>(
            g_Hbf + ((size_t)b * TT + th * 64) * MM) + mpair;
#pragma unroll 8
        for (int t2 = 0; t2 < 64; t2++) {
            float2 hv = __bfloat1622float2(hrow[(size_t)t2 * (MM / 2)]);
            float beta = sh_beta[th * 64 + t2];
            cx += beta * hv.x;
            cy += beta * hv.y;
        }
    }
    sh_px[tid] = cx;
    sh_py[tid] = cy;
    __syncthreads();
    float ctx;
    {
        const float* src = (tid & 1) ? sh_py : sh_px;
        int mp = tid >> 1;
        ctx = src[mp] + src[128 + mp];
    }
    __syncthreads();

    if (!final_mode) {
        sh_px[tid] = ctx * wt_w[1 + tid];
        __syncthreads();
        for (int off = 128; off > 0; off >>= 1) {
            if (tid < off) sh_px[tid] += sh_px[tid + off];
            __syncthreads();
        }
        if (tid == 0) {
            float y = dec_data[(size_t)b * TT + step];
            g_yt[b] = sh_px[0] + y * wt_w[0] + wt_b[0];
        }
        return;
    }

    sh_v[tid] = g_d[p][b * PP + tid];
    sh_v[256 + tid] = ctx;
    __syncthreads();
    float a = l1_b[tid];
    const float* w = l1_w + tid * 512;
#pragma unroll 8
    for (int k = 0; k < 512; k++) a += sh_v[k] * w[k];
    a = fmaxf(a, 0.f);
    sh_px[tid] = a * l2_w[tid];
    __syncthreads();
    for (int off = 128; off > 0; off >>= 1) {
        if (tid < off) sh_px[tid] += sh_px[tid + off];
        __syncthreads();
    }
    if (tid == 0) out[b] = sh_px[0] + l2_b[0];
}

// ---------------- decoder LSTM gates: tf32 MMA + fused act -------------------
__global__ __launch_bounds__(256) void dec_gates_act_kernel(
    const float* __restrict__ Wih, const float* __restrict__ Whh,
    const float* __restrict__ bih, const float* __restrict__ bhh, int p)
{
    __shared__ uint32_t As[64][20];
    __shared__ uint32_t Bs[16][72];
    __shared__ float Sg[64][68];
    const int j0 = blockIdx.x * 16;
    const int b0 = blockIdx.y * 64;
    const int tid = threadIdx.x;
    const int lane = tid & 31;
    const int warp = tid >> 5;
    const int mw = (warp & 3) * 16;
    const int nw = (warp >> 2) * 32;
    const int gid = lane >> 2;
    const int tig = lane & 3;

    const float* d_in = g_d[p];
    const float* s_in = g_s[p];
    float* d_out = g_d[p ^ 1];
    float* s_out = g_s[p ^ 1];

    float acc[4][4];
#pragma unroll
    for (int i = 0; i < 4; i++)
#pragma unroll
        for (int j = 0; j < 4; j++) acc[i][j] = 0.f;

    for (int c = 0; c < 16; c++) {
        int k0 = c * 16;
#pragma unroll
        for (int i = 0; i < 4; i++) {
            int idx = tid + i * 256;
            int m = idx >> 4, k = idx & 15;
            As[m][k] = f2tf32(d_in[(b0 + m) * PP + k0 + k]);
        }
#pragma unroll
        for (int i = 0; i < 4; i++) {
            int idx = tid + i * 256;
            int cc = idx >> 4, k = idx & 15;
            int jj = cc >> 2, gate = cc & 3;
            Bs[k][cc] = f2tf32(Whh[(gate * 256 + j0 + jj) * PP + k0 + k]);
        }
        __syncthreads();
#pragma unroll
        for (int ks = 0; ks < 16; ks += 8) {
            uint32_t a0 = As[mw + gid][ks + tig];
            uint32_t a1 = As[mw + 8 + gid][ks + tig];
            uint32_t a2 = As[mw + gid][ks + 4 + tig];
            uint32_t a3 = As[mw + 8 + gid][ks + 4 + tig];
#pragma unroll
            for (int nt = 0; nt < 4; nt++) {
                uint32_t b0r = Bs[ks + tig][nw + nt * 8 + gid];
                uint32_t b1r = Bs[ks + 4 + tig][nw + nt * 8 + gid];
                mma_tf32(acc[nt], a0, a1, a2, a3, b0r, b1r);
            }
        }
        __syncthreads();
    }

#pragma unroll
    for (int nt = 0; nt < 4; nt++) {
        int col = nw + nt * 8 + tig * 2;
        int row = mw + gid;
        Sg[row][col]     = acc[nt][0];
        Sg[row][col + 1] = acc[nt][1];
        Sg[row + 8][col]     = acc[nt][2];
        Sg[row + 8][col + 1] = acc[nt][3];
    }
    __syncthreads();

    {
        int r = tid & 63;
        int b = b0 + r;
        float yt = g_yt[b];
#pragma unroll
        for (int jj = tid >> 6; jj < 16; jj += 4) {
            float4 g4 = *reinterpret_cast<const float4*>(&Sg[r][jj * 4]);
            int col0 = j0 + jj;
            float gi = g4.x + yt * Wih[col0]       + bih[col0]       + bhh[col0];
            float gf = g4.y + yt * Wih[256 + col0] + bih[256 + col0] + bhh[256 + col0];
            float gg = g4.z + yt * Wih[512 + col0] + bih[512 + col0] + bhh[512 + col0];
            float go = g4.w + yt * Wih[768 + col0] + bih[768 + col0] + bhh[768 + col0];
            int sidx = b * PP + col0;
            float s_old = s_in[sidx];
            float sn = fsig(gf) * s_old + fsig(gi) * ftanh(gg);
            float dn = fsig(go) * ftanh(sn);
            s_out[sidx] = sn;
            d_out[sidx] = dn;
        }
    }
}

// ---------------- launch -----------------------------------------------------
extern "C" void kernel_launch(void* const* d_in, const int* in_sizes, int n_in,
                              void* d_out, int out_size)
{
    const float* enc_data = (const float*)d_in[0];
    const float* dec_data = (const float*)d_in[1];
    const float* enc_Wih  = (const float*)d_in[2];
    const float* enc_Whh  = (const float*)d_in[3];
    const float* enc_bih  = (const float*)d_in[4];
    const float* enc_bhh  = (const float*)d_in[5];
    const float* We       = (const float*)d_in[6];
    const float* Ue       = (const float*)d_in[7];
    const float* ve       = (const float*)d_in[8];
    const float* Wd       = (const float*)d_in[9];
    const float* Ud       = (const float*)d_in[10];
    const float* vd       = (const float*)d_in[11];
    const float* wt_w     = (const float*)d_in[12];
    const float* wt_b     = (const float*)d_in[13];
    const float* dec_Wih  = (const float*)d_in[14];
    const float* dec_Whh  = (const float*)d_in[15];
    const float* dec_bih  = (const float*)d_in[16];
    const float* dec_bhh  = (const float*)d_in[17];
    const float* l1_w     = (const float*)d_in[18];
    const float* l1_b     = (const float*)d_in[19];
    const float* l2_w     = (const float*)d_in[20];
    const float* l2_b     = (const float*)d_in[21];
    float* out = (float*)d_out;

    ue_pre_kernel<<<dim3(NN / 64, TT / 64, BB), 256>>>(enc_data, Ue);

    for (int t = 0; t < TT; t++) {
        int p = t & 1;
        enc_wq_kernel<<<dim3(TT / 64, BB / 64, 4), 256>>>(We, p);
        enc_attn_kernel<<<BB, 256>>>(enc_data, ve, t);
        enc_gates_act_kernel<<<dim3(16, 16), 256>>>(enc_Wih, enc_Whh, enc_bih, enc_bhh, t, p);
    }

    uh_pre_kernel<<<dim3(TT / 64, MM / 64, BB), 256>>>(Ud);

    for (int step = 0; step < TT - 1; step++) {
        int p = step & 1;
        dec_wq_kernel<<<dim3(MM / 64, BB / 64, 4), 256>>>(Wd, p);
        dec_attn_kernel<<<BB, 256>>>(dec_data, vd, wt_w, wt_b, step, 0, p,
                                     l1_w, l1_b, l2_w, l2_b, out);
        dec_gates_act_kernel<<<dim3(16, 16), 256>>>(dec_Wih, dec_Whh, dec_bih, dec_bhh, p);
    }

    // final attention + head with last decoder state (parity 127&1 = 1)
    dec_wq_kernel<<<dim3(MM / 64, BB / 64, 4), 256>>>(Wd, 1);
    dec_attn_kernel<<<BB, 256>>>(dec_data, vd, wt_w, wt_b, 0, 1, 1,
                                 l1_w, l1_b, l2_w, l2_b, out);
}